// round 3
// baseline (speedup 1.0000x reference)
#include <cuda_runtime.h>
#include <math.h>

#define BATCH 512
#define DIM   512
#define CLS   100000
#define CT    32     // classes per block
#define KC    16     // K chunk

// ---------------- persistent scratch (device globals; no allocations) -------
__device__ float g_xn[BATCH * DIM];   // normalized x, 1 MB
__device__ float g_gt[BATCH];
__device__ float g_thresh[BATCH];
__device__ float g_sumexp[BATCH];
__device__ float g_boost[BATCH];
__device__ int   g_cnt[BATCH];
__device__ int   g_is64;

// ---------------- label dtype sniffing --------------------------------------
// Reference asks for int64 labels; under default JAX config this silently
// becomes int32. Read only the first 2KB (in-bounds for both dtypes): if the
// data is int64 (labels < 1e5), every odd 32-bit word is 0; if int32, odd
// words are random labels and are essentially never all zero.
__global__ void k_detect(const int* __restrict__ lab32) {
    __shared__ int any;
    if (threadIdx.x == 0) any = 0;
    __syncthreads();
    int a = 0;
    for (int i = threadIdx.x; i < BATCH / 2; i += blockDim.x)
        if (lab32[2 * i + 1] != 0) a = 1;
    if (a) atomicOr(&any, 1);
    __syncthreads();
    if (threadIdx.x == 0) g_is64 = any ? 0 : 1;
}

__device__ __forceinline__ int load_label(const void* lab, int i, int is64) {
    return is64 ? (int)((const long long*)lab)[i] : ((const int*)lab)[i];
}

// ---------------- kernel 1: normalize x, gt/thresh, zero accumulators -------
// One block (128 threads) per batch row. Each thread owns 4 consecutive floats.
__global__ void k_prep(const float* __restrict__ x, const void* __restrict__ lab,
                       const float* __restrict__ W) {
    int row = blockIdx.x, tid = threadIdx.x;
    int is64 = g_is64;
    __shared__ float rsx[4], rsw[4], rdw[4];

    float4 xv = ((const float4*)(x + (size_t)row * DIM))[tid];
    int l = load_label(lab, row, is64);
    float4 wv = ((const float4*)(W + (size_t)l * DIM))[tid];

    float sx = xv.x * xv.x + xv.y * xv.y + xv.z * xv.z + xv.w * xv.w;
    float sw = wv.x * wv.x + wv.y * wv.y + wv.z * wv.z + wv.w * wv.w;
    float dw = xv.x * wv.x + xv.y * wv.y + xv.z * wv.z + xv.w * wv.w;
    #pragma unroll
    for (int o = 16; o; o >>= 1) {
        sx += __shfl_xor_sync(0xffffffffu, sx, o);
        sw += __shfl_xor_sync(0xffffffffu, sw, o);
        dw += __shfl_xor_sync(0xffffffffu, dw, o);
    }
    if ((tid & 31) == 0) { rsx[tid >> 5] = sx; rsw[tid >> 5] = sw; rdw[tid >> 5] = dw; }
    __syncthreads();
    float nx2 = rsx[0] + rsx[1] + rsx[2] + rsx[3];
    float nw2 = rsw[0] + rsw[1] + rsw[2] + rsw[3];
    float dot = rdw[0] + rdw[1] + rdw[2] + rdw[3];

    float invx = 1.0f / fmaxf(sqrtf(nx2), 1e-12f);
    float4 o4 = make_float4(xv.x * invx, xv.y * invx, xv.z * invx, xv.w * invx);
    ((float4*)(g_xn + (size_t)row * DIM))[tid] = o4;

    if (tid == 0) {
        const float M0 = 0.4f;
        float invw = 1.0f / fmaxf(sqrtf(nw2), 1e-12f);
        float gt = fminf(fmaxf(dot * invx * invw, -1.0f), 1.0f);
        g_gt[row] = gt;
        // cos(acos(g)+m0) = g cos m0 - sqrt(1-g^2) sin m0  (exact identity)
        g_thresh[row] = gt * cosf(M0) - sqrtf(fmaxf(0.0f, 1.0f - gt * gt)) * sinf(M0);
        g_sumexp[row] = 0.0f;
        g_boost[row]  = 0.0f;
        g_cnt[row]    = 0;
    }
}

// ---------------- kernel 2: fused cos GEMM + mask/boost/exp scan ------------
// Block = CT=32 classes x all 512 rows. 256 threads: cg = tid&7 (4 classes
// each), rg = tid>>3 (16 rows each) -> 64 fp32 accumulators per thread.
// K streamed in 16-wide chunks through smem (x transposed for conflict-free
// reads). W row-norms accumulated on the fly by the W-loader threads.
__global__ void __launch_bounds__(256, 2)
k_main(const void* __restrict__ lab, const float* __restrict__ W) {
    __shared__ float xs[KC][BATCH];  // 32 KB (xs[k][row])
    __shared__ float ws[KC][CT];     // 2 KB  (ws[k][class])
    __shared__ float wsq[CT];
    __shared__ float thr[BATCH];
    __shared__ int   lbl[BATCH];

    int tid = threadIdx.x;
    int cg = tid & 7;          // class group: classes cg*4 .. cg*4+3
    int rg = tid >> 3;         // row group:   rows rg*16 .. rg*16+15
    int cbase = blockIdx.x * CT;
    int is64 = g_is64;

    for (int i = tid; i < BATCH; i += 256) {
        lbl[i] = load_label(lab, i, is64);
        thr[i] = g_thresh[i];
    }

    float acc[16][4];
    #pragma unroll
    for (int i = 0; i < 16; i++)
        #pragma unroll
        for (int j = 0; j < 4; j++) acc[i][j] = 0.0f;

    float wsqp = 0.0f;
    int c_w = tid >> 2, q_w = tid & 3;  // W loaders: 4 threads per class

    for (int kc = 0; kc < DIM / KC; kc++) {
        int k0 = kc * KC;
        // load x chunk, transposed: xs[k][row]. Stores are conflict-free
        // (32 consecutive rows per warp at fixed k -> 32 distinct banks).
        #pragma unroll
        for (int s = 0; s < 2; s++) {
            int row = tid + s * 256;
            const float4* src = (const float4*)(g_xn + (size_t)row * DIM + k0);
            float4 a0 = src[0], a1 = src[1], a2 = src[2], a3 = src[3];
            xs[0][row]  = a0.x; xs[1][row]  = a0.y; xs[2][row]  = a0.z; xs[3][row]  = a0.w;
            xs[4][row]  = a1.x; xs[5][row]  = a1.y; xs[6][row]  = a1.z; xs[7][row]  = a1.w;
            xs[8][row]  = a2.x; xs[9][row]  = a2.y; xs[10][row] = a2.z; xs[11][row] = a2.w;
            xs[12][row] = a3.x; xs[13][row] = a3.y; xs[14][row] = a3.z; xs[15][row] = a3.w;
        }
        // load W chunk + accumulate squared norm partials
        if (tid < 128) {
            const float4* src =
                (const float4*)(W + (size_t)(cbase + c_w) * DIM + k0 + q_w * 4);
            float4 wv = src[0];
            wsqp += wv.x * wv.x + wv.y * wv.y + wv.z * wv.z + wv.w * wv.w;
            int kb = q_w * 4;
            ws[kb + 0][c_w] = wv.x; ws[kb + 1][c_w] = wv.y;
            ws[kb + 2][c_w] = wv.z; ws[kb + 3][c_w] = wv.w;
        }
        __syncthreads();

        #pragma unroll
        for (int kk = 0; kk < KC; kk++) {
            float4 wv = *(const float4*)&ws[kk][cg * 4];
            const float4* xp = (const float4*)&xs[kk][rg * 16];
            float4 x0 = xp[0], x1 = xp[1], x2 = xp[2], x3 = xp[3];
            float xr[16] = {x0.x, x0.y, x0.z, x0.w, x1.x, x1.y, x1.z, x1.w,
                            x2.x, x2.y, x2.z, x2.w, x3.x, x3.y, x3.z, x3.w};
            #pragma unroll
            for (int i = 0; i < 16; i++) {
                acc[i][0] += xr[i] * wv.x;
                acc[i][1] += xr[i] * wv.y;
                acc[i][2] += xr[i] * wv.z;
                acc[i][3] += xr[i] * wv.w;
            }
        }
        __syncthreads();
    }

    // finalize per-class squared norms
    if (tid < 128) {
        wsqp += __shfl_xor_sync(0xffffffffu, wsqp, 1);
        wsqp += __shfl_xor_sync(0xffffffffu, wsqp, 2);
        if (q_w == 0) wsq[c_w] = wsqp;
    }
    __syncthreads();

    // epilogue: clip -> mask -> boost -> exp, reduce across the 8 class-group
    // lanes sharing each row, 3 global atomics per (block,row).
    const float S = 32.0f, T = 1.1f, ALPHA = 0.25f;
    float invw[4]; int cls[4];
    #pragma unroll
    for (int j = 0; j < 4; j++) {
        invw[j] = 1.0f / fmaxf(sqrtf(wsq[cg * 4 + j]), 1e-12f);
        cls[j] = cbase + cg * 4 + j;
    }
    #pragma unroll
    for (int i = 0; i < 16; i++) {
        int r = rg * 16 + i;
        float th = thr[r];
        int lb = lbl[r];
        float se = 0.0f, bs = 0.0f;
        int ct = 0;
        #pragma unroll
        for (int j = 0; j < 4; j++) {
            if (cls[j] == lb) continue;  // gt column handled in finalize
            float cosv = fminf(fmaxf(acc[i][j] * invw[j], -1.0f), 1.0f);
            bool hard = cosv > th;
            float val = hard ? (T * cosv + ALPHA) : cosv;
            se += expf(S * val);  // logits in [-32, 43.2]: no overflow in fp32
            if (hard) { ct++; bs += val; }
        }
        #pragma unroll
        for (int o = 1; o <= 4; o <<= 1) {
            se += __shfl_xor_sync(0xffffffffu, se, o);
            bs += __shfl_xor_sync(0xffffffffu, bs, o);
            ct += __shfl_xor_sync(0xffffffffu, ct, o);
        }
        if (cg == 0) {
            atomicAdd(&g_sumexp[r], se);
            atomicAdd(&g_boost[r], bs);
            atomicAdd(&g_cnt[r], ct);
        }
    }
}

// ---------------- kernel 3: margin, LSE, mean CE, focal ---------------------
__global__ void k_fin(float* __restrict__ out) {
    int i = threadIdx.x;  // 512 threads, one per row
    const float M0 = 0.4f, M1 = 0.2f, S = 32.0f;
    float gt = g_gt[i];
    float se = g_sumexp[i];
    float bs = g_boost[i];
    int   ct = g_cnt[i];

    float lam = bs / fmaxf((float)ct, 1.0f);
    float mi = M0 + (ct > 0 ? lam * M1 : 0.0f);
    float cosm = gt * cosf(mi) - sqrtf(fmaxf(0.0f, 1.0f - gt * gt)) * sinf(mi);
    float fgt = (gt > 0.0f) ? cosm : gt;
    float lgt = S * fgt;
    float c = logf(se + expf(lgt)) - lgt;  // per-row (LSE - gt logit)

    __shared__ float red[16];
    #pragma unroll
    for (int o = 16; o; o >>= 1) c += __shfl_xor_sync(0xffffffffu, c, o);
    if ((i & 31) == 0) red[i >> 5] = c;
    __syncthreads();
    if (i == 0) {
        float s = 0.0f;
        #pragma unroll
        for (int w = 0; w < 16; w++) s += red[w];
        float logp = s / (float)BATCH;
        float p = expf(-logp);
        float om = 1.0f - p;
        out[0] = om * om * logp;  // gamma = 2
    }
}

// ---------------- launch ----------------------------------------------------
extern "C" void kernel_launch(void* const* d_in, const int* in_sizes, int n_in,
                              void* d_out, int out_size) {
    const float* x = (const float*)d_in[0];
    const void*  lab = d_in[1];
    const float* W = (const float*)d_in[2];
    (void)in_sizes; (void)n_in; (void)out_size;

    k_detect<<<1, 256>>>((const int*)lab);
    k_prep<<<BATCH, 128>>>(x, lab, W);
    k_main<<<CLS / CT, 256>>>(lab, W);
    k_fin<<<1, BATCH>>>((float*)d_out);
}

// round 4
// speedup vs baseline: 1.0009x; 1.0009x over previous
#include <cuda_runtime.h>
#include <math.h>

#define BATCH 512
#define DIM   512
#define CLS   100000
#define CT    32     // classes per block
#define KC    16     // K chunk

// ---------------- persistent scratch (device globals; no allocations) -------
__device__ float g_xn[BATCH * DIM];   // normalized x, 1 MB
__device__ float g_gt[BATCH];
__device__ float g_thresh[BATCH];
__device__ float g_sumexp[BATCH];
__device__ float g_boost[BATCH];
__device__ int   g_cnt[BATCH];
__device__ int   g_is64;

// ---------------- label dtype sniffing --------------------------------------
// Reference asks for int64 labels; under default JAX config this silently
// becomes int32. Read only the first 2KB (in-bounds for both dtypes): if the
// data is int64 (labels < 1e5), every odd 32-bit word is 0; if int32, odd
// words are random labels and are essentially never all zero.
__global__ void k_detect(const int* __restrict__ lab32) {
    __shared__ int any;
    if (threadIdx.x == 0) any = 0;
    __syncthreads();
    int a = 0;
    for (int i = threadIdx.x; i < BATCH / 2; i += blockDim.x)
        if (lab32[2 * i + 1] != 0) a = 1;
    if (a) atomicOr(&any, 1);
    __syncthreads();
    if (threadIdx.x == 0) g_is64 = any ? 0 : 1;
}

__device__ __forceinline__ int load_label(const void* lab, int i, int is64) {
    return is64 ? (int)((const long long*)lab)[i] : ((const int*)lab)[i];
}

// ---------------- kernel 1: normalize x, gt/thresh, zero accumulators -------
// One block (128 threads) per batch row. Each thread owns 4 consecutive floats.
__global__ void k_prep(const float* __restrict__ x, const void* __restrict__ lab,
                       const float* __restrict__ W) {
    int row = blockIdx.x, tid = threadIdx.x;
    int is64 = g_is64;
    __shared__ float rsx[4], rsw[4], rdw[4];

    float4 xv = ((const float4*)(x + (size_t)row * DIM))[tid];
    int l = load_label(lab, row, is64);
    float4 wv = ((const float4*)(W + (size_t)l * DIM))[tid];

    float sx = xv.x * xv.x + xv.y * xv.y + xv.z * xv.z + xv.w * xv.w;
    float sw = wv.x * wv.x + wv.y * wv.y + wv.z * wv.z + wv.w * wv.w;
    float dw = xv.x * wv.x + xv.y * wv.y + xv.z * wv.z + xv.w * wv.w;
    #pragma unroll
    for (int o = 16; o; o >>= 1) {
        sx += __shfl_xor_sync(0xffffffffu, sx, o);
        sw += __shfl_xor_sync(0xffffffffu, sw, o);
        dw += __shfl_xor_sync(0xffffffffu, dw, o);
    }
    if ((tid & 31) == 0) { rsx[tid >> 5] = sx; rsw[tid >> 5] = sw; rdw[tid >> 5] = dw; }
    __syncthreads();
    float nx2 = rsx[0] + rsx[1] + rsx[2] + rsx[3];
    float nw2 = rsw[0] + rsw[1] + rsw[2] + rsw[3];
    float dot = rdw[0] + rdw[1] + rdw[2] + rdw[3];

    float invx = 1.0f / fmaxf(sqrtf(nx2), 1e-12f);
    float4 o4 = make_float4(xv.x * invx, xv.y * invx, xv.z * invx, xv.w * invx);
    ((float4*)(g_xn + (size_t)row * DIM))[tid] = o4;

    if (tid == 0) {
        const float M0 = 0.4f;
        float invw = 1.0f / fmaxf(sqrtf(nw2), 1e-12f);
        float gt = fminf(fmaxf(dot * invx * invw, -1.0f), 1.0f);
        g_gt[row] = gt;
        // cos(acos(g)+m0) = g cos m0 - sqrt(1-g^2) sin m0  (exact identity)
        g_thresh[row] = gt * cosf(M0) - sqrtf(fmaxf(0.0f, 1.0f - gt * gt)) * sinf(M0);
        g_sumexp[row] = 0.0f;
        g_boost[row]  = 0.0f;
        g_cnt[row]    = 0;
    }
}

// ---------------- kernel 2: fused cos GEMM + mask/boost/exp scan ------------
// Block = CT=32 classes x all 512 rows. 256 threads: cg = tid&7 (4 classes
// each), rg = tid>>3 (16 rows each) -> 64 fp32 accumulators per thread.
// K streamed in 16-wide chunks through smem (x transposed for conflict-free
// reads). W row-norms accumulated on the fly by the W-loader threads.
__global__ void __launch_bounds__(256, 2)
k_main(const void* __restrict__ lab, const float* __restrict__ W) {
    __shared__ float xs[KC][BATCH];  // 32 KB (xs[k][row])
    __shared__ float ws[KC][CT];     // 2 KB  (ws[k][class])
    __shared__ float wsq[CT];
    __shared__ float thr[BATCH];
    __shared__ int   lbl[BATCH];

    int tid = threadIdx.x;
    int cg = tid & 7;          // class group: classes cg*4 .. cg*4+3
    int rg = tid >> 3;         // row group:   rows rg*16 .. rg*16+15
    int cbase = blockIdx.x * CT;
    int is64 = g_is64;

    for (int i = tid; i < BATCH; i += 256) {
        lbl[i] = load_label(lab, i, is64);
        thr[i] = g_thresh[i];
    }

    float acc[16][4];
    #pragma unroll
    for (int i = 0; i < 16; i++)
        #pragma unroll
        for (int j = 0; j < 4; j++) acc[i][j] = 0.0f;

    float wsqp = 0.0f;
    int c_w = tid >> 2, q_w = tid & 3;  // W loaders: 4 threads per class

    for (int kc = 0; kc < DIM / KC; kc++) {
        int k0 = kc * KC;
        // load x chunk, transposed: xs[k][row]. Stores are conflict-free
        // (32 consecutive rows per warp at fixed k -> 32 distinct banks).
        #pragma unroll
        for (int s = 0; s < 2; s++) {
            int row = tid + s * 256;
            const float4* src = (const float4*)(g_xn + (size_t)row * DIM + k0);
            float4 a0 = src[0], a1 = src[1], a2 = src[2], a3 = src[3];
            xs[0][row]  = a0.x; xs[1][row]  = a0.y; xs[2][row]  = a0.z; xs[3][row]  = a0.w;
            xs[4][row]  = a1.x; xs[5][row]  = a1.y; xs[6][row]  = a1.z; xs[7][row]  = a1.w;
            xs[8][row]  = a2.x; xs[9][row]  = a2.y; xs[10][row] = a2.z; xs[11][row] = a2.w;
            xs[12][row] = a3.x; xs[13][row] = a3.y; xs[14][row] = a3.z; xs[15][row] = a3.w;
        }
        // load W chunk + accumulate squared norm partials
        if (tid < 128) {
            const float4* src =
                (const float4*)(W + (size_t)(cbase + c_w) * DIM + k0 + q_w * 4);
            float4 wv = src[0];
            wsqp += wv.x * wv.x + wv.y * wv.y + wv.z * wv.z + wv.w * wv.w;
            int kb = q_w * 4;
            ws[kb + 0][c_w] = wv.x; ws[kb + 1][c_w] = wv.y;
            ws[kb + 2][c_w] = wv.z; ws[kb + 3][c_w] = wv.w;
        }
        __syncthreads();

        #pragma unroll
        for (int kk = 0; kk < KC; kk++) {
            float4 wv = *(const float4*)&ws[kk][cg * 4];
            const float4* xp = (const float4*)&xs[kk][rg * 16];
            float4 x0 = xp[0], x1 = xp[1], x2 = xp[2], x3 = xp[3];
            float xr[16] = {x0.x, x0.y, x0.z, x0.w, x1.x, x1.y, x1.z, x1.w,
                            x2.x, x2.y, x2.z, x2.w, x3.x, x3.y, x3.z, x3.w};
            #pragma unroll
            for (int i = 0; i < 16; i++) {
                acc[i][0] += xr[i] * wv.x;
                acc[i][1] += xr[i] * wv.y;
                acc[i][2] += xr[i] * wv.z;
                acc[i][3] += xr[i] * wv.w;
            }
        }
        __syncthreads();
    }

    // finalize per-class squared norms
    if (tid < 128) {
        wsqp += __shfl_xor_sync(0xffffffffu, wsqp, 1);
        wsqp += __shfl_xor_sync(0xffffffffu, wsqp, 2);
        if (q_w == 0) wsq[c_w] = wsqp;
    }
    __syncthreads();

    // epilogue: clip -> mask -> boost -> exp, reduce across the 8 class-group
    // lanes sharing each row, 3 global atomics per (block,row).
    const float S = 32.0f, T = 1.1f, ALPHA = 0.25f;
    float invw[4]; int cls[4];
    #pragma unroll
    for (int j = 0; j < 4; j++) {
        invw[j] = 1.0f / fmaxf(sqrtf(wsq[cg * 4 + j]), 1e-12f);
        cls[j] = cbase + cg * 4 + j;
    }
    #pragma unroll
    for (int i = 0; i < 16; i++) {
        int r = rg * 16 + i;
        float th = thr[r];
        int lb = lbl[r];
        float se = 0.0f, bs = 0.0f;
        int ct = 0;
        #pragma unroll
        for (int j = 0; j < 4; j++) {
            if (cls[j] == lb) continue;  // gt column handled in finalize
            float cosv = fminf(fmaxf(acc[i][j] * invw[j], -1.0f), 1.0f);
            bool hard = cosv > th;
            float val = hard ? (T * cosv + ALPHA) : cosv;
            se += expf(S * val);  // logits in [-32, 43.2]: no overflow in fp32
            if (hard) { ct++; bs += val; }
        }
        #pragma unroll
        for (int o = 1; o <= 4; o <<= 1) {
            se += __shfl_xor_sync(0xffffffffu, se, o);
            bs += __shfl_xor_sync(0xffffffffu, bs, o);
            ct += __shfl_xor_sync(0xffffffffu, ct, o);
        }
        if (cg == 0) {
            atomicAdd(&g_sumexp[r], se);
            atomicAdd(&g_boost[r], bs);
            atomicAdd(&g_cnt[r], ct);
        }
    }
}

// ---------------- kernel 3: margin, LSE, mean CE, focal ---------------------
__global__ void k_fin(float* __restrict__ out) {
    int i = threadIdx.x;  // 512 threads, one per row
    const float M0 = 0.4f, M1 = 0.2f, S = 32.0f;
    float gt = g_gt[i];
    float se = g_sumexp[i];
    float bs = g_boost[i];
    int   ct = g_cnt[i];

    float lam = bs / fmaxf((float)ct, 1.0f);
    float mi = M0 + (ct > 0 ? lam * M1 : 0.0f);
    float cosm = gt * cosf(mi) - sqrtf(fmaxf(0.0f, 1.0f - gt * gt)) * sinf(mi);
    float fgt = (gt > 0.0f) ? cosm : gt;
    float lgt = S * fgt;
    float c = logf(se + expf(lgt)) - lgt;  // per-row (LSE - gt logit)

    __shared__ float red[16];
    #pragma unroll
    for (int o = 16; o; o >>= 1) c += __shfl_xor_sync(0xffffffffu, c, o);
    if ((i & 31) == 0) red[i >> 5] = c;
    __syncthreads();
    if (i == 0) {
        float s = 0.0f;
        #pragma unroll
        for (int w = 0; w < 16; w++) s += red[w];
        float logp = s / (float)BATCH;
        float p = expf(-logp);
        float om = 1.0f - p;
        out[0] = om * om * logp;  // gamma = 2
    }
}

// ---------------- launch ----------------------------------------------------
extern "C" void kernel_launch(void* const* d_in, const int* in_sizes, int n_in,
                              void* d_out, int out_size) {
    const float* x = (const float*)d_in[0];
    const void*  lab = d_in[1];
    const float* W = (const float*)d_in[2];
    (void)in_sizes; (void)n_in; (void)out_size;

    k_detect<<<1, 256>>>((const int*)lab);
    k_prep<<<BATCH, 128>>>(x, lab, W);
    k_main<<<CLS / CT, 256>>>(lab, W);
    k_fin<<<1, BATCH>>>((float*)d_out);
}